// round 4
// baseline (speedup 1.0000x reference)
#include <cuda_runtime.h>
#include <math_constants.h>

#define NB      64          // batches
#define HW      262144      // 512*512 per batch
#define WIDTH   512
#define CHUNKS  16
#define TPB     256
#define NBLOCKS (NB * CHUNKS)                  // 1024
#define ELEMS_PER_CHUNK (HW / CHUNKS)          // 16384
#define VEC4_PER_CHUNK  (ELEMS_PER_CHUNK / 4)  // 4096
#define ITERS   (VEC4_PER_CHUNK / TPB)         // 16
#define UF      4                              // load batch (8 LDG.128 in flight)
#define GROUPS  (ITERS / UF)                   // 4

// Scratch (device globals — no allocation allowed)
__device__ float g_pmax[NBLOCKS];
__device__ int   g_pidx[NBLOCKS];
__device__ float g_lmax[NBLOCKS];
__device__ int   g_lidx[NBLOCKS];
__device__ float g_sq  [NBLOCKS];
__device__ unsigned int g_count = 0;

__device__ __forceinline__ void amax_upd(float v, int ix, float& m, int& mi) {
    if (v > m || (v == m && ix < mi)) { m = v; mi = ix; }
}

__global__ void __launch_bounds__(TPB, 4) loss_fused(
    const float* __restrict__ pred, const float* __restrict__ label,
    float* __restrict__ out)
{
    const int b = blockIdx.y;
    const int c = blockIdx.x;
    const int t = threadIdx.x;

    const float4* __restrict__ p4 = (const float4*)(pred  + (size_t)b * HW);
    const float4* __restrict__ l4 = (const float4*)(label + (size_t)b * HW);
    const int base4 = c * VEC4_PER_CHUNK;

    // two independent accumulator chains each
    float pm0 = -CUDART_INF_F, pm1 = -CUDART_INF_F; int pi0 = 0, pi1 = 0;
    float lm0 = -CUDART_INF_F, lm1 = -CUDART_INF_F; int li0 = 0, li1 = 0;
    float ss0 = 0.0f, ss1 = 0.0f;

    #pragma unroll
    for (int g = 0; g < GROUPS; ++g) {
        float4 P[UF], L[UF];
        // batch all loads first -> 8 outstanding LDG.128 (needs >32 regs!)
        #pragma unroll
        for (int u = 0; u < UF; ++u) {
            const int i4 = base4 + (g * UF + u) * TPB + t;
            P[u] = __ldcs(&p4[i4]);
            L[u] = __ldcs(&l4[i4]);
        }
        #pragma unroll
        for (int u = 0; u < UF; ++u) {
            const int idx = (base4 + (g * UF + u) * TPB + t) * 4;
            float pv[4] = {P[u].x, P[u].y, P[u].z, P[u].w};
            float lv[4] = {L[u].x, L[u].y, L[u].z, L[u].w};
            if (u & 1) {
                #pragma unroll
                for (int j = 0; j < 4; ++j) {
                    float d = pv[j] - lv[j];
                    ss1 = fmaf(d, d, ss1);
                    if (pv[j] > pm1) { pm1 = pv[j]; pi1 = idx + j; }
                    if (lv[j] > lm1) { lm1 = lv[j]; li1 = idx + j; }
                }
            } else {
                #pragma unroll
                for (int j = 0; j < 4; ++j) {
                    float d = pv[j] - lv[j];
                    ss0 = fmaf(d, d, ss0);
                    if (pv[j] > pm0) { pm0 = pv[j]; pi0 = idx + j; }
                    if (lv[j] > lm0) { lm0 = lv[j]; li0 = idx + j; }
                }
            }
        }
    }

    // merge the two chains (chain 1 indexes are larger within equal values? no —
    // interleaved, so use full tie-break compare which is order-independent)
    float pm = pm0; int pi = pi0;
    amax_upd(pm1, pi1, pm, pi);
    float lm = lm0; int li = li0;
    amax_upd(lm1, li1, lm, li);
    float ss = ss0 + ss1;

    __shared__ float spm[TPB]; __shared__ int spi[TPB];
    __shared__ float slm[TPB]; __shared__ int sli[TPB];
    __shared__ float sss[TPB];
    spm[t] = pm; spi[t] = pi;
    slm[t] = lm; sli[t] = li;
    sss[t] = ss;
    __syncthreads();

    #pragma unroll
    for (int s = TPB / 2; s > 0; s >>= 1) {
        if (t < s) {
            if (spm[t+s] > spm[t] || (spm[t+s] == spm[t] && spi[t+s] < spi[t])) {
                spm[t] = spm[t+s]; spi[t] = spi[t+s];
            }
            if (slm[t+s] > slm[t] || (slm[t+s] == slm[t] && sli[t+s] < sli[t])) {
                slm[t] = slm[t+s]; sli[t] = sli[t+s];
            }
            sss[t] += sss[t+s];
        }
        __syncthreads();
    }

    __shared__ bool is_last;
    if (t == 0) {
        const int o = b * CHUNKS + c;
        g_pmax[o] = spm[0]; g_pidx[o] = spi[0];
        g_lmax[o] = slm[0]; g_lidx[o] = sli[0];
        g_sq[o]   = sss[0];
        __threadfence();
        unsigned int n = atomicAdd(&g_count, 1u);
        is_last = (n == NBLOCKS - 1);
    }
    __syncthreads();
    if (!is_last) return;

    // ---- final reduction (partials are L2-hot) ----
    {
        const int fb = t >> 2;        // batch 0..63
        const int cg = t & 3;         // chunk group 0..3

        float fpm = -CUDART_INF_F; int fpi = 0;
        float flm = -CUDART_INF_F; int fli = 0;
        float fss = 0.0f;

        #pragma unroll
        for (int k = 0; k < 4; ++k) {
            const int o = fb * CHUNKS + cg * 4 + k;
            amax_upd(g_pmax[o], g_pidx[o], fpm, fpi);
            amax_upd(g_lmax[o], g_lidx[o], flm, fli);
            fss += g_sq[o];
        }

        #pragma unroll
        for (int off = 2; off > 0; off >>= 1) {
            float v  = __shfl_down_sync(0xffffffffu, fpm, off, 4);
            int   ix = __shfl_down_sync(0xffffffffu, fpi, off, 4);
            amax_upd(v, ix, fpm, fpi);
            v  = __shfl_down_sync(0xffffffffu, flm, off, 4);
            ix = __shfl_down_sync(0xffffffffu, fli, off, 4);
            amax_upd(v, ix, flm, fli);
            fss += __shfl_down_sync(0xffffffffu, fss, off, 4);
        }

        __shared__ float sidx[64];
        __shared__ float smse[64];
        if (cg == 0) {
            const float rp = (float)(fpi / WIDTH), cp = (float)(fpi % WIDTH);
            const float rl = (float)(fli / WIDTH), cl = (float)(fli % WIDTH);
            const float dr = rp - rl, dc = cp - cl;
            sidx[fb] = dr * dr + dc * dc;
            smse[fb] = fss;
        }
        __syncthreads();

        if (t < 32) {
            float I = sidx[t] + sidx[t + 32];
            float M = smse[t] + smse[t + 32];
            #pragma unroll
            for (int off = 16; off > 0; off >>= 1) {
                I += __shfl_down_sync(0xffffffffu, I, off);
                M += __shfl_down_sync(0xffffffffu, M, off);
            }
            if (t == 0) {
                const float alpha = (I != 0.0f) ? (M / I) : 1.0f;
                out[0] = (M + 0.25f * alpha * I) / (float)NB;
                g_count = 0;  // reset for next graph replay
            }
        }
    }
}

extern "C" void kernel_launch(void* const* d_in, const int* in_sizes, int n_in,
                              void* d_out, int out_size)
{
    const float* pred  = (const float*)d_in[0];
    const float* label = (const float*)d_in[1];
    float* out = (float*)d_out;

    dim3 grid(CHUNKS, NB);
    loss_fused<<<grid, TPB>>>(pred, label, out);
}

// round 5
// speedup vs baseline: 1.2382x; 1.2382x over previous
#include <cuda_runtime.h>
#include <math_constants.h>

#define NB      64          // batches
#define HW      262144      // 512*512 per batch
#define WIDTH   512
#define CHUNKS  16
#define TPB     256
#define NBLOCKS (NB * CHUNKS)                  // 1024
#define VEC4_PER_CHUNK  (HW / CHUNKS / 4)      // 4096
#define ITERS   (VEC4_PER_CHUNK / TPB)         // 16
#define UF      2                              // 4 LDG.128 batched
#define GROUPS  (ITERS / UF)                   // 8

// Scratch (device globals — no allocation allowed)
__device__ float g_pmax[NBLOCKS];
__device__ int   g_pidx[NBLOCKS];
__device__ float g_lmax[NBLOCKS];
__device__ int   g_lidx[NBLOCKS];
__device__ float g_sq  [NBLOCKS];
__device__ unsigned int g_count = 0;

__device__ __forceinline__ void amax_upd(float v, int ix, float& m, int& mi) {
    if (v > m || (v == m && ix < mi)) { m = v; mi = ix; }
}

// value+pos argmax combine (pos monotone with flat idx => exact first-occurrence)
__device__ __forceinline__ void vpos_upd(float v, int p, float& m, int& mp) {
    if (v > m || (v == m && p < mp)) { m = v; mp = p; }
}

__global__ void __launch_bounds__(TPB, 6) loss_fused(
    const float* __restrict__ pred, const float* __restrict__ label,
    float* __restrict__ out)
{
    const int b = blockIdx.y;
    const int c = blockIdx.x;
    const int t = threadIdx.x;

    const float4* __restrict__ p4 = (const float4*)(pred  + (size_t)b * HW);
    const float4* __restrict__ l4 = (const float4*)(label + (size_t)b * HW);
    const int base4 = c * VEC4_PER_CHUNK;

    float pm = -CUDART_INF_F; int ppos = 0;   // pos = it*TPB + t (float4 granularity)
    float lm = -CUDART_INF_F; int lpos = 0;
    float ss = 0.0f;

    #pragma unroll
    for (int g = 0; g < GROUPS; ++g) {
        float4 P[UF], L[UF];
        #pragma unroll
        for (int u = 0; u < UF; ++u) {
            const int i4 = base4 + (g * UF + u) * TPB + t;
            P[u] = p4[i4];
            L[u] = l4[i4];
        }
        #pragma unroll
        for (int u = 0; u < UF; ++u) {
            const int it = g * UF + u;
            const int pos = it * TPB + t;
            // mse: 4 sub + 4 fma
            float d0 = P[u].x - L[u].x, d1 = P[u].y - L[u].y;
            float d2 = P[u].z - L[u].z, d3 = P[u].w - L[u].w;
            ss = fmaf(d0, d0, ss); ss = fmaf(d1, d1, ss);
            ss = fmaf(d2, d2, ss); ss = fmaf(d3, d3, ss);
            // argmax: FMNMX tree + single pos update (strict > keeps earliest it)
            float pmax4 = fmaxf(fmaxf(P[u].x, P[u].y), fmaxf(P[u].z, P[u].w));
            if (pmax4 > pm) { pm = pmax4; ppos = pos; }
            float lmax4 = fmaxf(fmaxf(L[u].x, L[u].y), fmaxf(L[u].z, L[u].w));
            if (lmax4 > lm) { lm = lmax4; lpos = pos; }
        }
    }

    // ---- block reduction: warp shuffles, then cross-warp via smem ----
    const unsigned FULL = 0xffffffffu;
    #pragma unroll
    for (int off = 16; off > 0; off >>= 1) {
        float v; int p;
        v = __shfl_down_sync(FULL, pm, off); p = __shfl_down_sync(FULL, ppos, off);
        vpos_upd(v, p, pm, ppos);
        v = __shfl_down_sync(FULL, lm, off); p = __shfl_down_sync(FULL, lpos, off);
        vpos_upd(v, p, lm, lpos);
        ss += __shfl_down_sync(FULL, ss, off);
    }

    __shared__ float wpm[8]; __shared__ int wpp[8];
    __shared__ float wlm[8]; __shared__ int wlp[8];
    __shared__ float wss[8];
    const int warp = t >> 5, lane = t & 31;
    if (lane == 0) {
        wpm[warp] = pm; wpp[warp] = ppos;
        wlm[warp] = lm; wlp[warp] = lpos;
        wss[warp] = ss;
    }
    __syncthreads();

    __shared__ bool is_last;
    if (t == 0) {
        float bpm = wpm[0]; int bpp = wpp[0];
        float blm = wlm[0]; int blp = wlp[0];
        float bss = wss[0];
        #pragma unroll
        for (int w = 1; w < 8; ++w) {
            vpos_upd(wpm[w], wpp[w], bpm, bpp);
            vpos_upd(wlm[w], wlp[w], blm, blp);
            bss += wss[w];
        }
        // recover exact element index: reload winning float4s (issue both first)
        const float4 Pw = p4[base4 + bpp];
        const float4 Lw = l4[base4 + blp];
        int pj = 3;                       // smallest j with equality wins
        if (Pw.w == bpm) pj = 3; if (Pw.z == bpm) pj = 2;
        if (Pw.y == bpm) pj = 1; if (Pw.x == bpm) pj = 0;
        int lj = 3;
        if (Lw.w == blm) lj = 3; if (Lw.z == blm) lj = 2;
        if (Lw.y == blm) lj = 1; if (Lw.x == blm) lj = 0;

        const int o = b * CHUNKS + c;
        g_pmax[o] = bpm; g_pidx[o] = (base4 + bpp) * 4 + pj;
        g_lmax[o] = blm; g_lidx[o] = (base4 + blp) * 4 + lj;
        g_sq[o]   = bss;
        __threadfence();
        unsigned int n = atomicAdd(&g_count, 1u);
        is_last = (n == NBLOCKS - 1);
    }
    __syncthreads();
    if (!is_last) return;

    // ---- final reduction (partials are L2-hot) ----
    {
        const int fb = t >> 2;        // batch 0..63
        const int cg = t & 3;         // chunk group 0..3

        float fpm = -CUDART_INF_F; int fpi = 0;
        float flm = -CUDART_INF_F; int fli = 0;
        float fss = 0.0f;

        #pragma unroll
        for (int k = 0; k < 4; ++k) {
            const int o = fb * CHUNKS + cg * 4 + k;
            amax_upd(g_pmax[o], g_pidx[o], fpm, fpi);
            amax_upd(g_lmax[o], g_lidx[o], flm, fli);
            fss += g_sq[o];
        }

        #pragma unroll
        for (int off = 2; off > 0; off >>= 1) {
            float v  = __shfl_down_sync(FULL, fpm, off, 4);
            int   ix = __shfl_down_sync(FULL, fpi, off, 4);
            amax_upd(v, ix, fpm, fpi);
            v  = __shfl_down_sync(FULL, flm, off, 4);
            ix = __shfl_down_sync(FULL, fli, off, 4);
            amax_upd(v, ix, flm, fli);
            fss += __shfl_down_sync(FULL, fss, off, 4);
        }

        __shared__ float sidx[64];
        __shared__ float smse[64];
        if (cg == 0) {
            const float rp = (float)(fpi / WIDTH), cp = (float)(fpi % WIDTH);
            const float rl = (float)(fli / WIDTH), cl = (float)(fli % WIDTH);
            const float dr = rp - rl, dc = cp - cl;
            sidx[fb] = dr * dr + dc * dc;
            smse[fb] = fss;
        }
        __syncthreads();

        if (t < 32) {
            float I = sidx[t] + sidx[t + 32];
            float M = smse[t] + smse[t + 32];
            #pragma unroll
            for (int off = 16; off > 0; off >>= 1) {
                I += __shfl_down_sync(FULL, I, off);
                M += __shfl_down_sync(FULL, M, off);
            }
            if (t == 0) {
                const float alpha = (I != 0.0f) ? (M / I) : 1.0f;
                out[0] = (M + 0.25f * alpha * I) / (float)NB;
                g_count = 0;  // reset for next graph replay
            }
        }
    }
}

extern "C" void kernel_launch(void* const* d_in, const int* in_sizes, int n_in,
                              void* d_out, int out_size)
{
    const float* pred  = (const float*)d_in[0];
    const float* label = (const float*)d_in[1];
    float* out = (float*)d_out;

    dim3 grid(CHUNKS, NB);
    loss_fused<<<grid, TPB>>>(pred, label, out);
}